// round 1
// baseline (speedup 1.0000x reference)
#include <cuda_runtime.h>
#include <math_constants.h>

#define DIM 1024
#define NQ  8192
#define NM  8192

// Scratch (allocation-free rule: __device__ globals)
__device__ float g_Q[(size_t)NQ * DIM];                 // 32 MB
__device__ float g_K[(size_t)NM * DIM];                 // 32 MB
__device__ float g_V[(size_t)NM * DIM];                 // 32 MB
__device__ float g_S[(size_t)NQ * NM];                  // 256 MB

// ---------------------------------------------------------------------------
// Tiled FP32 GEMM: C[M,N] = alpha * A[M,K] @ op(B) (+ bias)
//   TRANS_B = false : B is [K,N] row-major
//   TRANS_B = true  : B is [N,K] row-major (computes A @ B^T)
// BM=BN=128, BK=16, 256 threads, 8x8 micro-tile per thread.
// Requires M%128==0, N%128==0, K%16==0 (all shapes here satisfy this).
// ---------------------------------------------------------------------------
template <bool TRANS_B, bool HAS_BIAS>
__global__ void __launch_bounds__(256)
sgemm128(const float* __restrict__ A, const float* __restrict__ B,
         const float* __restrict__ bias, float* __restrict__ C,
         int M, int N, int K, float alpha)
{
    __shared__ float As[16][128];   // As[k][m]
    __shared__ float Bs[16][128];   // Bs[k][n]

    const int tid = threadIdx.x;
    const int tx  = tid & 15;       // 0..15 -> 8 output cols each
    const int ty  = tid >> 4;       // 0..15 -> 8 output rows each
    const int row0 = blockIdx.y * 128;
    const int col0 = blockIdx.x * 128;

    float acc[8][8];
#pragma unroll
    for (int i = 0; i < 8; i++)
#pragma unroll
        for (int j = 0; j < 8; j++) acc[i][j] = 0.0f;

    for (int kt = 0; kt < K; kt += 16) {
        // ---- load A tile (128 rows x 16 cols), store transposed ----
#pragma unroll
        for (int i = 0; i < 2; i++) {
            int j  = tid + i * 256;          // 0..511 float4s
            int m  = j >> 2;
            int kq = (j & 3) * 4;
            float4 a = *reinterpret_cast<const float4*>(
                &A[(size_t)(row0 + m) * K + kt + kq]);
            As[kq + 0][m] = a.x;
            As[kq + 1][m] = a.y;
            As[kq + 2][m] = a.z;
            As[kq + 3][m] = a.w;
        }
        // ---- load B tile ----
        if (TRANS_B) {
            // B[N,K]: need rows col0..col0+127, cols kt..kt+15 (like A tile)
#pragma unroll
            for (int i = 0; i < 2; i++) {
                int j  = tid + i * 256;
                int n  = j >> 2;
                int kq = (j & 3) * 4;
                float4 b = *reinterpret_cast<const float4*>(
                    &B[(size_t)(col0 + n) * K + kt + kq]);
                Bs[kq + 0][n] = b.x;
                Bs[kq + 1][n] = b.y;
                Bs[kq + 2][n] = b.z;
                Bs[kq + 3][n] = b.w;
            }
        } else {
            // B[K,N]: rows kt..kt+15, cols col0..col0+127
#pragma unroll
            for (int i = 0; i < 2; i++) {
                int j  = tid + i * 256;
                int k  = j >> 5;
                int nq = (j & 31) * 4;
                *reinterpret_cast<float4*>(&Bs[k][nq]) =
                    *reinterpret_cast<const float4*>(
                        &B[(size_t)(kt + k) * N + col0 + nq]);
            }
        }
        __syncthreads();

        // ---- compute ----
#pragma unroll
        for (int kk = 0; kk < 16; kk++) {
            float a[8], b[8];
            *reinterpret_cast<float4*>(&a[0]) =
                *reinterpret_cast<const float4*>(&As[kk][ty * 8]);
            *reinterpret_cast<float4*>(&a[4]) =
                *reinterpret_cast<const float4*>(&As[kk][ty * 8 + 4]);
            *reinterpret_cast<float4*>(&b[0]) =
                *reinterpret_cast<const float4*>(&Bs[kk][tx * 8]);
            *reinterpret_cast<float4*>(&b[4]) =
                *reinterpret_cast<const float4*>(&Bs[kk][tx * 8 + 4]);
#pragma unroll
            for (int i = 0; i < 8; i++)
#pragma unroll
                for (int j = 0; j < 8; j++)
                    acc[i][j] = fmaf(a[i], b[j], acc[i][j]);
        }
        __syncthreads();
    }

    // ---- epilogue ----
#pragma unroll
    for (int i = 0; i < 8; i++) {
        const int r = row0 + ty * 8 + i;
#pragma unroll
        for (int jv = 0; jv < 2; jv++) {
            const int c = col0 + tx * 8 + jv * 4;
            float4 o;
            o.x = acc[i][jv * 4 + 0] * alpha;
            o.y = acc[i][jv * 4 + 1] * alpha;
            o.z = acc[i][jv * 4 + 2] * alpha;
            o.w = acc[i][jv * 4 + 3] * alpha;
            if (HAS_BIAS) {
                o.x += bias[c + 0];
                o.y += bias[c + 1];
                o.z += bias[c + 2];
                o.w += bias[c + 3];
            }
            *reinterpret_cast<float4*>(&C[(size_t)r * N + c]) = o;
        }
    }
}

// ---------------------------------------------------------------------------
// In-place row softmax. One block per row. Row length = 8192, 256 threads,
// 32 elements (8 float4) per thread, held in registers across both passes.
// ---------------------------------------------------------------------------
__global__ void __launch_bounds__(256)
softmax_rows(float* __restrict__ S, int M)
{
    const int tid  = threadIdx.x;
    const int lane = tid & 31;
    const int warp = tid >> 5;
    float* row = S + (size_t)blockIdx.x * M;

    float4 v[8];
#pragma unroll
    for (int j = 0; j < 8; j++)
        v[j] = *reinterpret_cast<const float4*>(&row[(tid + j * 256) * 4]);

    // -- max --
    float mx = -CUDART_INF_F;
#pragma unroll
    for (int j = 0; j < 8; j++) {
        mx = fmaxf(mx, fmaxf(fmaxf(v[j].x, v[j].y), fmaxf(v[j].z, v[j].w)));
    }
#pragma unroll
    for (int o = 16; o > 0; o >>= 1)
        mx = fmaxf(mx, __shfl_xor_sync(0xffffffffu, mx, o));

    __shared__ float red_max[8];
    __shared__ float red_sum[8];
    if (lane == 0) red_max[warp] = mx;
    __syncthreads();
    if (tid < 32) {
        float t = (tid < 8) ? red_max[tid] : -CUDART_INF_F;
#pragma unroll
        for (int o = 4; o > 0; o >>= 1)
            t = fmaxf(t, __shfl_xor_sync(0xffffffffu, t, o));
        if (tid == 0) red_max[0] = t;
    }
    __syncthreads();
    mx = red_max[0];

    // -- exp + sum --
    float s = 0.0f;
#pragma unroll
    for (int j = 0; j < 8; j++) {
        v[j].x = expf(v[j].x - mx);
        v[j].y = expf(v[j].y - mx);
        v[j].z = expf(v[j].z - mx);
        v[j].w = expf(v[j].w - mx);
        s += v[j].x + v[j].y + v[j].z + v[j].w;
    }
#pragma unroll
    for (int o = 16; o > 0; o >>= 1)
        s += __shfl_xor_sync(0xffffffffu, s, o);
    if (lane == 0) red_sum[warp] = s;
    __syncthreads();
    if (tid < 32) {
        float t = (tid < 8) ? red_sum[tid] : 0.0f;
#pragma unroll
        for (int o = 4; o > 0; o >>= 1)
            t += __shfl_xor_sync(0xffffffffu, t, o);
        if (tid == 0) red_sum[0] = t;
    }
    __syncthreads();
    const float inv = 1.0f / red_sum[0];

#pragma unroll
    for (int j = 0; j < 8; j++) {
        v[j].x *= inv; v[j].y *= inv; v[j].z *= inv; v[j].w *= inv;
        *reinterpret_cast<float4*>(&row[(tid + j * 256) * 4]) = v[j];
    }
}

// ---------------------------------------------------------------------------
// Launch: Q/K/V projections -> scores -> softmax -> output
// ---------------------------------------------------------------------------
extern "C" void kernel_launch(void* const* d_in, const int* in_sizes, int n_in,
                              void* d_out, int out_size)
{
    const float* x   = (const float*)d_in[0];
    const float* ctx = (const float*)d_in[1];
    const float* Wq  = (const float*)d_in[2];
    const float* bq  = (const float*)d_in[3];
    const float* Wk  = (const float*)d_in[4];
    const float* bk  = (const float*)d_in[5];
    const float* Wv  = (const float*)d_in[6];
    const float* bv  = (const float*)d_in[7];
    float* out = (float*)d_out;

    float *Q, *K, *V, *S;
    cudaGetSymbolAddress((void**)&Q, g_Q);
    cudaGetSymbolAddress((void**)&K, g_K);
    cudaGetSymbolAddress((void**)&V, g_V);
    cudaGetSymbolAddress((void**)&S, g_S);

    const dim3 blk(256);
    const float scale = 0.03125f;   // 1/sqrt(1024)

    // Projections: [*,1024] @ [1024,1024] + bias
    sgemm128<false, true><<<dim3(DIM / 128, NQ / 128), blk>>>(x,   Wq, bq, Q, NQ, DIM, DIM, 1.0f);
    sgemm128<false, true><<<dim3(DIM / 128, NM / 128), blk>>>(ctx, Wk, bk, K, NM, DIM, DIM, 1.0f);
    sgemm128<false, true><<<dim3(DIM / 128, NM / 128), blk>>>(ctx, Wv, bv, V, NM, DIM, DIM, 1.0f);

    // Scores: S = scale * Q @ K^T   [8192, 8192]
    sgemm128<true, false><<<dim3(NM / 128, NQ / 128), blk>>>(Q, K, nullptr, S, NQ, NM, DIM, scale);

    // Softmax rows in place
    softmax_rows<<<NQ, blk>>>(S, NM);

    // Output: out = P @ V   [8192, 1024]
    sgemm128<false, false><<<dim3(DIM / 128, NQ / 128), blk>>>(S, V, nullptr, out, NQ, DIM, NM, 1.0f);
}

// round 5
// speedup vs baseline: 2.4376x; 2.4376x over previous
#include <cuda_runtime.h>
#include <math_constants.h>
#include <cstdint>

#define DIM 1024
#define NQ  8192
#define NM  8192

// Scratch (allocation-free rule: __device__ globals)
__device__ float g_Q[(size_t)NQ * DIM];                 // 32 MB
__device__ float g_K[(size_t)NM * DIM];                 // 32 MB
__device__ float g_V[(size_t)NM * DIM];                 // 32 MB
__device__ float g_S[(size_t)NQ * NM];                  // 256 MB

// ---------------------------------------------------------------------------
// Tile config
// ---------------------------------------------------------------------------
static constexpr int BM = 128, BN = 128, BK = 32;
static constexpr int A_STRIDE = BK + 4;      // 36 floats/row, 144B (16B aligned)
static constexpr int BN_STRIDE = BN + 8;     // 136 floats/row, 544B (16B aligned)
static constexpr int ASZ = BM * A_STRIDE;    // floats per A buffer (4608)
static constexpr int BSZ = ASZ;              // B buffer sized to max of both layouts
static constexpr int SMEM_FLOATS = 2 * ASZ + 2 * BSZ;          // 18432
static constexpr int SMEM_BYTES  = SMEM_FLOATS * 4;            // 73728

// Round fp32 bit-pattern to tf32 (round-to-nearest-away): +half-ULP then HW
// truncation of the low 13 mantissa bits. Carry into exponent is correct.
__device__ __forceinline__ uint32_t rna_tf32(float f) {
    return __float_as_uint(f) + 0x1000u;
}

__device__ __forceinline__ void cp_async16(uint32_t smem_addr, const void* gptr) {
    asm volatile("cp.async.cg.shared.global [%0], [%1], 16;"
                 :: "r"(smem_addr), "l"(gptr));
}
__device__ __forceinline__ void cp_commit() {
    asm volatile("cp.async.commit_group;");
}
__device__ __forceinline__ void cp_wait1() {
    asm volatile("cp.async.wait_group 1;");
}

__device__ __forceinline__ uint32_t smem_u32(const void* p) {
    uint32_t a;
    asm("{ .reg .u64 t; cvta.to.shared.u64 t, %1; cvt.u32.u64 %0, t; }"
        : "=r"(a) : "l"(p));
    return a;
}

__device__ __forceinline__ void mma_tf32(float* c, const uint32_t* a, const uint32_t* b) {
    asm volatile(
        "mma.sync.aligned.m16n8k8.row.col.f32.tf32.tf32.f32 "
        "{%0,%1,%2,%3}, {%4,%5,%6,%7}, {%8,%9}, {%0,%1,%2,%3};"
        : "+f"(c[0]), "+f"(c[1]), "+f"(c[2]), "+f"(c[3])
        : "r"(a[0]), "r"(a[1]), "r"(a[2]), "r"(a[3]), "r"(b[0]), "r"(b[1]));
}

// ---------------------------------------------------------------------------
// TF32 mma.sync GEMM: C[M,N] = alpha * A[M,K] @ op(B) (+ bias)
//   TRANS_B=true : B is [N,K] row-major (A @ B^T)  -> Bs stored [n][k] like As
//   TRANS_B=false: B is [K,N] row-major            -> Bs stored [k][n]
// 256 threads, warp tile 64x32 (warps 2m x 4n), m16n8k8 fragments.
// M,N % 128 == 0, K % 32 == 0.
// ---------------------------------------------------------------------------
template <bool TRANS_B, bool HAS_BIAS>
__global__ void __launch_bounds__(256, 2)
mma_gemm(const float* __restrict__ A, const float* __restrict__ B,
         const float* __restrict__ bias, float* __restrict__ C,
         int M, int N, int K, float alpha)
{
    extern __shared__ __align__(16) float smem[];
    float* As = smem;                  // [2][BM][A_STRIDE]
    float* Bs = smem + 2 * ASZ;        // [2][...]

    const int tid  = threadIdx.x;
    const int wid  = tid >> 5;
    const int lane = tid & 31;
    const int gid  = lane >> 2;        // group id 0..7
    const int tig  = lane & 3;         // thread-in-group 0..3
    const int row0 = blockIdx.y * BM;
    const int col0 = blockIdx.x * BN;
    const int m0   = (wid & 1) * 64;   // warp m offset
    const int n0   = (wid >> 1) * 32;  // warp n offset

    const uint32_t s_as = smem_u32(As);
    const uint32_t s_bs = smem_u32(Bs);

    float acc[4][4][4];
#pragma unroll
    for (int i = 0; i < 4; i++)
#pragma unroll
        for (int j = 0; j < 4; j++)
#pragma unroll
            for (int r = 0; r < 4; r++) acc[i][j][r] = 0.0f;

    const int T = K / BK;

    // ---- tile loader (cp.async, 4 x 16B per thread per operand) ----
    auto load_tile = [&](int t) {
        const int buf = t & 1;
        const int kt  = t * BK;
        // A: 128 rows x 8 chunks of 16B
#pragma unroll
        for (int i = 0; i < 4; i++) {
            const int j  = tid * 4 + i;
            const int r  = j >> 3;
            const int ck = j & 7;
            cp_async16(s_as + (buf * ASZ + r * A_STRIDE + ck * 4) * 4,
                       &A[(size_t)(row0 + r) * K + kt + ck * 4]);
        }
        if (TRANS_B) {
            // B[N,K] rows col0.. : same pattern as A
#pragma unroll
            for (int i = 0; i < 4; i++) {
                const int j  = tid * 4 + i;
                const int r  = j >> 3;
                const int ck = j & 7;
                cp_async16(s_bs + (buf * BSZ + r * A_STRIDE + ck * 4) * 4,
                           &B[(size_t)(col0 + r) * K + kt + ck * 4]);
            }
        } else {
            // B[K,N]: 32 rows x 32 chunks of 16B
#pragma unroll
            for (int i = 0; i < 4; i++) {
                const int j  = tid * 4 + i;
                const int r  = j >> 5;
                const int ck = j & 31;
                cp_async16(s_bs + (buf * BSZ + r * BN_STRIDE + ck * 4) * 4,
                           &B[(size_t)(kt + r) * N + col0 + ck * 4]);
            }
        }
    };

    load_tile(0);
    cp_commit();

    for (int t = 0; t < T; ++t) {
        if (t + 1 < T) load_tile(t + 1);
        cp_commit();
        cp_wait1();
        __syncthreads();

        const float* At = As + (t & 1) * ASZ;
        const float* Bt = Bs + (t & 1) * BSZ;

#pragma unroll
        for (int ks = 0; ks < 4; ks++) {
            const int k = ks * 8;
            uint32_t af[4][4];
#pragma unroll
            for (int i = 0; i < 4; i++) {
                const int m = m0 + i * 16;
                af[i][0] = rna_tf32(At[(m + gid)     * A_STRIDE + k + tig]);
                af[i][1] = rna_tf32(At[(m + gid + 8) * A_STRIDE + k + tig]);
                af[i][2] = rna_tf32(At[(m + gid)     * A_STRIDE + k + tig + 4]);
                af[i][3] = rna_tf32(At[(m + gid + 8) * A_STRIDE + k + tig + 4]);
            }
            uint32_t bf[4][2];
#pragma unroll
            for (int j = 0; j < 4; j++) {
                const int n = n0 + j * 8;
                if (TRANS_B) {
                    bf[j][0] = rna_tf32(Bt[(n + gid) * A_STRIDE + k + tig]);
                    bf[j][1] = rna_tf32(Bt[(n + gid) * A_STRIDE + k + tig + 4]);
                } else {
                    bf[j][0] = rna_tf32(Bt[(k + tig)     * BN_STRIDE + n + gid]);
                    bf[j][1] = rna_tf32(Bt[(k + tig + 4) * BN_STRIDE + n + gid]);
                }
            }
#pragma unroll
            for (int i = 0; i < 4; i++)
#pragma unroll
                for (int j = 0; j < 4; j++)
                    mma_tf32(acc[i][j], af[i], bf[j]);
        }
        __syncthreads();
    }

    // ---- epilogue ----
#pragma unroll
    for (int i = 0; i < 4; i++) {
        const int r_lo = row0 + m0 + i * 16 + gid;
        const int r_hi = r_lo + 8;
#pragma unroll
        for (int j = 0; j < 4; j++) {
            const int c = col0 + n0 + j * 8 + tig * 2;
            float2 lo, hi;
            lo.x = acc[i][j][0] * alpha;
            lo.y = acc[i][j][1] * alpha;
            hi.x = acc[i][j][2] * alpha;
            hi.y = acc[i][j][3] * alpha;
            if (HAS_BIAS) {
                const float2 bb = *reinterpret_cast<const float2*>(&bias[c]);
                lo.x += bb.x; lo.y += bb.y;
                hi.x += bb.x; hi.y += bb.y;
            }
            *reinterpret_cast<float2*>(&C[(size_t)r_lo * N + c]) = lo;
            *reinterpret_cast<float2*>(&C[(size_t)r_hi * N + c]) = hi;
        }
    }
}

// ---------------------------------------------------------------------------
// In-place row softmax (unchanged, verified)
// ---------------------------------------------------------------------------
__global__ void __launch_bounds__(256)
softmax_rows(float* __restrict__ S, int M)
{
    const int tid  = threadIdx.x;
    const int lane = tid & 31;
    const int warp = tid >> 5;
    float* row = S + (size_t)blockIdx.x * M;

    float4 v[8];
#pragma unroll
    for (int j = 0; j < 8; j++)
        v[j] = *reinterpret_cast<const float4*>(&row[(tid + j * 256) * 4]);

    float mx = -CUDART_INF_F;
#pragma unroll
    for (int j = 0; j < 8; j++)
        mx = fmaxf(mx, fmaxf(fmaxf(v[j].x, v[j].y), fmaxf(v[j].z, v[j].w)));
#pragma unroll
    for (int o = 16; o > 0; o >>= 1)
        mx = fmaxf(mx, __shfl_xor_sync(0xffffffffu, mx, o));

    __shared__ float red_max[8];
    __shared__ float red_sum[8];
    if (lane == 0) red_max[warp] = mx;
    __syncthreads();
    if (tid < 32) {
        float t = (tid < 8) ? red_max[tid] : -CUDART_INF_F;
#pragma unroll
        for (int o = 4; o > 0; o >>= 1)
            t = fmaxf(t, __shfl_xor_sync(0xffffffffu, t, o));
        if (tid == 0) red_max[0] = t;
    }
    __syncthreads();
    mx = red_max[0];

    float s = 0.0f;
#pragma unroll
    for (int j = 0; j < 8; j++) {
        v[j].x = expf(v[j].x - mx);
        v[j].y = expf(v[j].y - mx);
        v[j].z = expf(v[j].z - mx);
        v[j].w = expf(v[j].w - mx);
        s += v[j].x + v[j].y + v[j].z + v[j].w;
    }
#pragma unroll
    for (int o = 16; o > 0; o >>= 1)
        s += __shfl_xor_sync(0xffffffffu, s, o);
    if (lane == 0) red_sum[warp] = s;
    __syncthreads();
    if (tid < 32) {
        float t = (tid < 8) ? red_sum[tid] : 0.0f;
#pragma unroll
        for (int o = 4; o > 0; o >>= 1)
            t += __shfl_xor_sync(0xffffffffu, t, o);
        if (tid == 0) red_sum[0] = t;
    }
    __syncthreads();
    const float inv = 1.0f / red_sum[0];

#pragma unroll
    for (int j = 0; j < 8; j++) {
        v[j].x *= inv; v[j].y *= inv; v[j].z *= inv; v[j].w *= inv;
        *reinterpret_cast<float4*>(&row[(tid + j * 256) * 4]) = v[j];
    }
}

// ---------------------------------------------------------------------------
extern "C" void kernel_launch(void* const* d_in, const int* in_sizes, int n_in,
                              void* d_out, int out_size)
{
    const float* x   = (const float*)d_in[0];
    const float* ctx = (const float*)d_in[1];
    const float* Wq  = (const float*)d_in[2];
    const float* bq  = (const float*)d_in[3];
    const float* Wk  = (const float*)d_in[4];
    const float* bk  = (const float*)d_in[5];
    const float* Wv  = (const float*)d_in[6];
    const float* bv  = (const float*)d_in[7];
    float* out = (float*)d_out;

    float *Q, *K, *V, *S;
    cudaGetSymbolAddress((void**)&Q, g_Q);
    cudaGetSymbolAddress((void**)&K, g_K);
    cudaGetSymbolAddress((void**)&V, g_V);
    cudaGetSymbolAddress((void**)&S, g_S);

    cudaFuncSetAttribute(mma_gemm<false, true>,
                         cudaFuncAttributeMaxDynamicSharedMemorySize, SMEM_BYTES);
    cudaFuncSetAttribute(mma_gemm<true, false>,
                         cudaFuncAttributeMaxDynamicSharedMemorySize, SMEM_BYTES);
    cudaFuncSetAttribute(mma_gemm<false, false>,
                         cudaFuncAttributeMaxDynamicSharedMemorySize, SMEM_BYTES);

    const dim3 blk(256);
    const float scale = 0.03125f;   // 1/sqrt(1024)

    // Projections
    mma_gemm<false, true><<<dim3(DIM / 128, NQ / 128), blk, SMEM_BYTES>>>(
        x,   Wq, bq, Q, NQ, DIM, DIM, 1.0f);
    mma_gemm<false, true><<<dim3(DIM / 128, NM / 128), blk, SMEM_BYTES>>>(
        ctx, Wk, bk, K, NM, DIM, DIM, 1.0f);
    mma_gemm<false, true><<<dim3(DIM / 128, NM / 128), blk, SMEM_BYTES>>>(
        ctx, Wv, bv, V, NM, DIM, DIM, 1.0f);

    // Scores: S = scale * Q @ K^T
    mma_gemm<true, false><<<dim3(NM / 128, NQ / 128), blk, SMEM_BYTES>>>(
        Q, K, nullptr, S, NQ, NM, DIM, scale);

    // Softmax
    softmax_rows<<<NQ, 256>>>(S, NM);

    // Output: out = P @ V
    mma_gemm<false, false><<<dim3(DIM / 128, NQ / 128), blk, SMEM_BYTES>>>(
        S, V, nullptr, out, NQ, DIM, NM, 1.0f);
}